// round 1
// baseline (speedup 1.0000x reference)
#include <cuda_runtime.h>
#include <math.h>

// Problem constants (fixed by the dataset)
#define DIM    1024
#define NEXP   4
#define BATCH  8
#define SEQ    4096
#define NPE    1024          // tokens per expert per batch
#define MROWS  8192          // BATCH * NPE  (GEMM M dim per expert)
#define INNER  4096

#define BM 128
#define BN 128
#define BK 16
#define SKW 20               // smem row length (16 + 4 pad), conflict-free frag loads

// Scratch (device globals: allocation-free per harness rules)
__device__ float g_h[(size_t)BATCH * SEQ * DIM];        // 128 MB: layernorm output
__device__ float g_inner[(size_t)MROWS * INNER];        // 128 MB: gelu(GEMM1) for one expert

// ---------------------------------------------------------------------------
// helpers
// ---------------------------------------------------------------------------
__device__ __forceinline__ unsigned f2tf32(float x) {
    unsigned r;
    asm("cvt.rna.tf32.f32 %0, %1;" : "=r"(r) : "f"(x));
    return r;
}

__device__ __forceinline__ void mma8(float* c, const unsigned* a, const unsigned* b) {
    asm volatile(
        "mma.sync.aligned.m16n8k8.row.col.f32.tf32.tf32.f32 "
        "{%0,%1,%2,%3}, {%4,%5,%6,%7}, {%8,%9}, {%0,%1,%2,%3};\n"
        : "+f"(c[0]), "+f"(c[1]), "+f"(c[2]), "+f"(c[3])
        : "r"(a[0]), "r"(a[1]), "r"(a[2]), "r"(a[3]), "r"(b[0]), "r"(b[1]));
}

__device__ __forceinline__ float gelu_exact(float v) {
    return 0.5f * v * (1.0f + erff(v * 0.70710678118654752f));
}

// local row r (0..8191) of expert e -> global token index
__device__ __forceinline__ size_t tok_of(int r, int e) {
    int b = r >> 10;
    int tt = r & 1023;
    return (size_t)b * SEQ + (size_t)e * NPE + tt;
}

// ---------------------------------------------------------------------------
// Kernel 1: LayerNorm (one block per token) + residual default out = x
// ---------------------------------------------------------------------------
__global__ void ln_kernel(const float* __restrict__ x,
                          const float* __restrict__ nw,
                          const float* __restrict__ nb,
                          float* __restrict__ out) {
    size_t g = blockIdx.x;
    int t = threadIdx.x;                       // 256 threads, 4 floats each
    const float4* xp = reinterpret_cast<const float4*>(x + g * DIM);
    float4 v = xp[t];
    float s  = v.x + v.y + v.z + v.w;
    float sq = v.x * v.x + v.y * v.y + v.z * v.z + v.w * v.w;
    #pragma unroll
    for (int o = 16; o; o >>= 1) {
        s  += __shfl_xor_sync(0xffffffffu, s,  o);
        sq += __shfl_xor_sync(0xffffffffu, sq, o);
    }
    __shared__ float ss[8], ssq[8];
    __shared__ float mu_s, rs_s;
    int wid = t >> 5, lid = t & 31;
    if (lid == 0) { ss[wid] = s; ssq[wid] = sq; }
    __syncthreads();
    if (t == 0) {
        float S = 0.f, SQ = 0.f;
        #pragma unroll
        for (int i = 0; i < 8; i++) { S += ss[i]; SQ += ssq[i]; }
        float mu = S * (1.0f / DIM);
        float var = SQ * (1.0f / DIM) - mu * mu;
        mu_s = mu;
        rs_s = rsqrtf(var + 1e-5f);
    }
    __syncthreads();
    float mu = mu_s, rs = rs_s;
    float4 wv = reinterpret_cast<const float4*>(nw)[t];
    float4 bv = reinterpret_cast<const float4*>(nb)[t];
    float4 h;
    h.x = (v.x - mu) * rs * wv.x + bv.x;
    h.y = (v.y - mu) * rs * wv.y + bv.y;
    h.z = (v.z - mu) * rs * wv.z + bv.z;
    h.w = (v.w - mu) * rs * wv.w + bv.w;
    reinterpret_cast<float4*>(g_h + g * DIM)[t] = h;
    reinterpret_cast<float4*>(out + g * DIM)[t] = v;   // default: residual passthrough
}

// ---------------------------------------------------------------------------
// GEMM core macro pieces are written out explicitly in each kernel
// (128x128x16 tile, 8 warps as 2(M) x 4(N), warp tile 64x32, m16n8k8 tf32)
// ---------------------------------------------------------------------------

// Kernel 2: inner = gelu( h[:, :K] @ l1_w[:, :K]^T + l1_b )
__global__ __launch_bounds__(256, 2)
void gemm1_kernel(const float* __restrict__ l1w,
                  const float* __restrict__ l1b,
                  int e, int K) {
    __shared__ unsigned As[2][BM][SKW];
    __shared__ unsigned Bs[2][BN][SKW];

    const int tid  = threadIdx.x;
    const int srow = tid >> 2;        // 0..63
    const int skq  = tid & 3;         // float4 index along K

    // global load pointers (row-major, K contiguous)
    const float* aptr0 = g_h + tok_of(blockIdx.y * BM + srow, e) * DIM + skq * 4;
    const float* aptr1 = g_h + tok_of(blockIdx.y * BM + srow + 64, e) * DIM + skq * 4;
    const float* bptr0 = l1w + (size_t)(blockIdx.x * BN + srow) * DIM + skq * 4;
    const float* bptr1 = bptr0 + (size_t)64 * DIM;

    float acc[4][4][4];
    #pragma unroll
    for (int i = 0; i < 4; i++)
        #pragma unroll
        for (int j = 0; j < 4; j++)
            #pragma unroll
            for (int k = 0; k < 4; k++) acc[i][j][k] = 0.f;

    // prologue: tile 0
    {
        float4 A0 = *(const float4*)aptr0;
        float4 A1 = *(const float4*)aptr1;
        float4 B0 = *(const float4*)bptr0;
        float4 B1 = *(const float4*)bptr1;
        As[0][srow   ][skq*4+0]=f2tf32(A0.x); As[0][srow   ][skq*4+1]=f2tf32(A0.y);
        As[0][srow   ][skq*4+2]=f2tf32(A0.z); As[0][srow   ][skq*4+3]=f2tf32(A0.w);
        As[0][srow+64][skq*4+0]=f2tf32(A1.x); As[0][srow+64][skq*4+1]=f2tf32(A1.y);
        As[0][srow+64][skq*4+2]=f2tf32(A1.z); As[0][srow+64][skq*4+3]=f2tf32(A1.w);
        Bs[0][srow   ][skq*4+0]=f2tf32(B0.x); Bs[0][srow   ][skq*4+1]=f2tf32(B0.y);
        Bs[0][srow   ][skq*4+2]=f2tf32(B0.z); Bs[0][srow   ][skq*4+3]=f2tf32(B0.w);
        Bs[0][srow+64][skq*4+0]=f2tf32(B1.x); Bs[0][srow+64][skq*4+1]=f2tf32(B1.y);
        Bs[0][srow+64][skq*4+2]=f2tf32(B1.z); Bs[0][srow+64][skq*4+3]=f2tf32(B1.w);
    }
    __syncthreads();

    const int wid   = tid >> 5;
    const int mBase = (wid & 1) * 64;
    const int nBase = (wid >> 1) * 32;
    const int lane  = tid & 31;
    const int lm    = lane >> 2;
    const int lk    = lane & 3;

    const int KT = K / BK;
    for (int kt = 0; kt < KT; ++kt) {
        const int cur = kt & 1, nxt = cur ^ 1;
        float4 A0, A1, B0, B1;
        const bool more = (kt + 1 < KT);
        if (more) {
            size_t off = (size_t)(kt + 1) * BK;
            A0 = *(const float4*)(aptr0 + off);
            A1 = *(const float4*)(aptr1 + off);
            B0 = *(const float4*)(bptr0 + off);
            B1 = *(const float4*)(bptr1 + off);
        }
        #pragma unroll
        for (int ks = 0; ks < 2; ++ks) {
            unsigned af[4][4], bf[4][2];
            #pragma unroll
            for (int mi = 0; mi < 4; mi++) {
                int m0 = mBase + mi * 16 + lm;
                af[mi][0] = As[cur][m0    ][ks*8 + lk    ];
                af[mi][1] = As[cur][m0 + 8][ks*8 + lk    ];
                af[mi][2] = As[cur][m0    ][ks*8 + lk + 4];
                af[mi][3] = As[cur][m0 + 8][ks*8 + lk + 4];
            }
            #pragma unroll
            for (int ni = 0; ni < 4; ni++) {
                int n0 = nBase + ni * 8 + lm;
                bf[ni][0] = Bs[cur][n0][ks*8 + lk    ];
                bf[ni][1] = Bs[cur][n0][ks*8 + lk + 4];
            }
            #pragma unroll
            for (int mi = 0; mi < 4; mi++)
                #pragma unroll
                for (int ni = 0; ni < 4; ni++)
                    mma8(acc[mi][ni], af[mi], bf[ni]);
        }
        if (more) {
            As[nxt][srow   ][skq*4+0]=f2tf32(A0.x); As[nxt][srow   ][skq*4+1]=f2tf32(A0.y);
            As[nxt][srow   ][skq*4+2]=f2tf32(A0.z); As[nxt][srow   ][skq*4+3]=f2tf32(A0.w);
            As[nxt][srow+64][skq*4+0]=f2tf32(A1.x); As[nxt][srow+64][skq*4+1]=f2tf32(A1.y);
            As[nxt][srow+64][skq*4+2]=f2tf32(A1.z); As[nxt][srow+64][skq*4+3]=f2tf32(A1.w);
            Bs[nxt][srow   ][skq*4+0]=f2tf32(B0.x); Bs[nxt][srow   ][skq*4+1]=f2tf32(B0.y);
            Bs[nxt][srow   ][skq*4+2]=f2tf32(B0.z); Bs[nxt][srow   ][skq*4+3]=f2tf32(B0.w);
            Bs[nxt][srow+64][skq*4+0]=f2tf32(B1.x); Bs[nxt][srow+64][skq*4+1]=f2tf32(B1.y);
            Bs[nxt][srow+64][skq*4+2]=f2tf32(B1.z); Bs[nxt][srow+64][skq*4+3]=f2tf32(B1.w);
        }
        __syncthreads();
    }

    // epilogue: bias + exact gelu -> g_inner
    const int rT = blockIdx.y * BM + mBase;
    const int cT = blockIdx.x * BN + nBase;
    #pragma unroll
    for (int mi = 0; mi < 4; mi++) {
        int r0 = rT + mi * 16 + lm;
        #pragma unroll
        for (int ni = 0; ni < 4; ni++) {
            int c0 = cT + ni * 8 + lk * 2;
            float bv0 = l1b[c0], bv1 = l1b[c0 + 1];
            float2 lo = make_float2(gelu_exact(acc[mi][ni][0] + bv0),
                                    gelu_exact(acc[mi][ni][1] + bv1));
            float2 hi = make_float2(gelu_exact(acc[mi][ni][2] + bv0),
                                    gelu_exact(acc[mi][ni][3] + bv1));
            *(float2*)&g_inner[(size_t)r0 * INNER + c0]       = lo;
            *(float2*)&g_inner[(size_t)(r0 + 8) * INNER + c0] = hi;
        }
    }
}

// Kernel 3: out[:, :m] = x + scale * ( inner @ l2_w[:m,:]^T + l2_b[:m] )
__global__ __launch_bounds__(256, 2)
void gemm2_kernel(const float* __restrict__ x,
                  const float* __restrict__ rp,
                  const float* __restrict__ alpha_p,
                  const float* __restrict__ l2w,
                  const float* __restrict__ l2b,
                  float* __restrict__ out,
                  int e) {
    __shared__ unsigned As[2][BM][SKW];
    __shared__ unsigned Bs[2][BN][SKW];

    const int tid  = threadIdx.x;
    const int srow = tid >> 2;
    const int skq  = tid & 3;

    const float* aptr0 = g_inner + (size_t)(blockIdx.y * BM + srow) * INNER + skq * 4;
    const float* aptr1 = aptr0 + (size_t)64 * INNER;
    const float* bptr0 = l2w + (size_t)(blockIdx.x * BN + srow) * INNER + skq * 4;
    const float* bptr1 = bptr0 + (size_t)64 * INNER;

    float acc[4][4][4];
    #pragma unroll
    for (int i = 0; i < 4; i++)
        #pragma unroll
        for (int j = 0; j < 4; j++)
            #pragma unroll
            for (int k = 0; k < 4; k++) acc[i][j][k] = 0.f;

    {
        float4 A0 = *(const float4*)aptr0;
        float4 A1 = *(const float4*)aptr1;
        float4 B0 = *(const float4*)bptr0;
        float4 B1 = *(const float4*)bptr1;
        As[0][srow   ][skq*4+0]=f2tf32(A0.x); As[0][srow   ][skq*4+1]=f2tf32(A0.y);
        As[0][srow   ][skq*4+2]=f2tf32(A0.z); As[0][srow   ][skq*4+3]=f2tf32(A0.w);
        As[0][srow+64][skq*4+0]=f2tf32(A1.x); As[0][srow+64][skq*4+1]=f2tf32(A1.y);
        As[0][srow+64][skq*4+2]=f2tf32(A1.z); As[0][srow+64][skq*4+3]=f2tf32(A1.w);
        Bs[0][srow   ][skq*4+0]=f2tf32(B0.x); Bs[0][srow   ][skq*4+1]=f2tf32(B0.y);
        Bs[0][srow   ][skq*4+2]=f2tf32(B0.z); Bs[0][srow   ][skq*4+3]=f2tf32(B0.w);
        Bs[0][srow+64][skq*4+0]=f2tf32(B1.x); Bs[0][srow+64][skq*4+1]=f2tf32(B1.y);
        Bs[0][srow+64][skq*4+2]=f2tf32(B1.z); Bs[0][srow+64][skq*4+3]=f2tf32(B1.w);
    }
    __syncthreads();

    const int wid   = tid >> 5;
    const int mBase = (wid & 1) * 64;
    const int nBase = (wid >> 1) * 32;
    const int lane  = tid & 31;
    const int lm    = lane >> 2;
    const int lk    = lane & 3;

    const int KT = INNER / BK;   // 256
    for (int kt = 0; kt < KT; ++kt) {
        const int cur = kt & 1, nxt = cur ^ 1;
        float4 A0, A1, B0, B1;
        const bool more = (kt + 1 < KT);
        if (more) {
            size_t off = (size_t)(kt + 1) * BK;
            A0 = *(const float4*)(aptr0 + off);
            A1 = *(const float4*)(aptr1 + off);
            B0 = *(const float4*)(bptr0 + off);
            B1 = *(const float4*)(bptr1 + off);
        }
        #pragma unroll
        for (int ks = 0; ks < 2; ++ks) {
            unsigned af[4][4], bf[4][2];
            #pragma unroll
            for (int mi = 0; mi < 4; mi++) {
                int m0 = mBase + mi * 16 + lm;
                af[mi][0] = As[cur][m0    ][ks*8 + lk    ];
                af[mi][1] = As[cur][m0 + 8][ks*8 + lk    ];
                af[mi][2] = As[cur][m0    ][ks*8 + lk + 4];
                af[mi][3] = As[cur][m0 + 8][ks*8 + lk + 4];
            }
            #pragma unroll
            for (int ni = 0; ni < 4; ni++) {
                int n0 = nBase + ni * 8 + lm;
                bf[ni][0] = Bs[cur][n0][ks*8 + lk    ];
                bf[ni][1] = Bs[cur][n0][ks*8 + lk + 4];
            }
            #pragma unroll
            for (int mi = 0; mi < 4; mi++)
                #pragma unroll
                for (int ni = 0; ni < 4; ni++)
                    mma8(acc[mi][ni], af[mi], bf[ni]);
        }
        if (more) {
            As[nxt][srow   ][skq*4+0]=f2tf32(A0.x); As[nxt][srow   ][skq*4+1]=f2tf32(A0.y);
            As[nxt][srow   ][skq*4+2]=f2tf32(A0.z); As[nxt][srow   ][skq*4+3]=f2tf32(A0.w);
            As[nxt][srow+64][skq*4+0]=f2tf32(A1.x); As[nxt][srow+64][skq*4+1]=f2tf32(A1.y);
            As[nxt][srow+64][skq*4+2]=f2tf32(A1.z); As[nxt][srow+64][skq*4+3]=f2tf32(A1.w);
            Bs[nxt][srow   ][skq*4+0]=f2tf32(B0.x); Bs[nxt][srow   ][skq*4+1]=f2tf32(B0.y);
            Bs[nxt][srow   ][skq*4+2]=f2tf32(B0.z); Bs[nxt][srow   ][skq*4+3]=f2tf32(B0.w);
            Bs[nxt][srow+64][skq*4+0]=f2tf32(B1.x); Bs[nxt][srow+64][skq*4+1]=f2tf32(B1.y);
            Bs[nxt][srow+64][skq*4+2]=f2tf32(B1.z); Bs[nxt][srow+64][skq*4+3]=f2tf32(B1.w);
        }
        __syncthreads();
    }

    // epilogue: scaled residual into out
    const float al = *alpha_p;
    const int rT = blockIdx.y * BM + mBase;
    const int cT = blockIdx.x * BN + nBase;
    #pragma unroll
    for (int mi = 0; mi < 4; mi++) {
        int rloc = rT + mi * 16 + lm;
        size_t g0 = tok_of(rloc, e);
        size_t g1 = tok_of(rloc + 8, e);
        float sc0 = al * rp[g0 * NEXP + e] + 1.0f;
        float sc1 = al * rp[g1 * NEXP + e] + 1.0f;
        #pragma unroll
        for (int ni = 0; ni < 4; ni++) {
            int c0 = cT + ni * 8 + lk * 2;
            float bv0 = l2b[c0], bv1 = l2b[c0 + 1];
            float2 xv0 = *(const float2*)&x[g0 * DIM + c0];
            float2 xv1 = *(const float2*)&x[g1 * DIM + c0];
            float2 o0 = make_float2(xv0.x + sc0 * (acc[mi][ni][0] + bv0),
                                    xv0.y + sc0 * (acc[mi][ni][1] + bv1));
            float2 o1 = make_float2(xv1.x + sc1 * (acc[mi][ni][2] + bv0),
                                    xv1.y + sc1 * (acc[mi][ni][3] + bv1));
            *(float2*)&out[g0 * DIM + c0] = o0;
            *(float2*)&out[g1 * DIM + c0] = o1;
        }
    }
}

// ---------------------------------------------------------------------------
extern "C" void kernel_launch(void* const* d_in, const int* in_sizes, int n_in,
                              void* d_out, int out_size) {
    const float* x     = (const float*)d_in[0];
    const float* rp    = (const float*)d_in[1];
    const float* alpha = (const float*)d_in[2];
    const float* nw    = (const float*)d_in[3];
    const float* nb    = (const float*)d_in[4];
    const float* l1w   = (const float*)d_in[5];
    const float* l1b   = (const float*)d_in[6];
    const float* l2w   = (const float*)d_in[7];
    const float* l2b   = (const float*)d_in[8];
    float* out = (float*)d_out;

    ln_kernel<<<BATCH * SEQ, 256>>>(x, nw, nb, out);

    for (int e = 0; e < NEXP; ++e) {
        int m = DIM >> e;
        dim3 g1(INNER / BN, MROWS / BM);   // (32, 64)
        gemm1_kernel<<<g1, 256>>>(l1w, l1b, e, m);
        dim3 g2(m / BN, MROWS / BM);       // (m/128, 64)
        gemm2_kernel<<<g2, 256>>>(x, rp, alpha, l2w, l2b, out, e);
    }
}

// round 2
// speedup vs baseline: 1.3832x; 1.3832x over previous
#include <cuda_runtime.h>
#include <math.h>

// Problem constants
#define DIM    1024
#define NEXP   4
#define BATCH  8
#define SEQ    4096
#define NPE    1024
#define MROWS  8192          // BATCH*NPE, GEMM M per expert
#define INNER  4096

#define BM 128
#define BN 128
#define BK 16
#define SKW 20               // smem words per 16-float row (pad 4): conflict-free LDSM/cp.async
#define STAGES 4
#define SMEM_FLOATS (2 * STAGES * 128 * SKW)
#define SMEM_BYTES  (SMEM_FLOATS * 4)

// Scratch device globals (allocation-free per harness rules)
__device__ float g_h[(size_t)BATCH * SEQ * DIM];            // 128 MB: rna-tf32 layernorm out
__device__ float g_inner[(size_t)NEXP * MROWS * INNER];     // 512 MB: per-expert gelu(GEMM1)
__device__ float g_w1[(size_t)INNER * DIM];                 // 16 MB: rna-tf32 l1_w
__device__ float g_w2[(size_t)DIM * INNER];                 // 16 MB: rna-tf32 l2_w

// ---------------------------------------------------------------------------
__device__ __forceinline__ unsigned f2tf32(float x) {
    unsigned r;
    asm("cvt.rna.tf32.f32 %0, %1;" : "=r"(r) : "f"(x));
    return r;
}
__device__ __forceinline__ float rna_tf32(float x) { return __uint_as_float(f2tf32(x)); }

__device__ __forceinline__ void mma8(float* c, const unsigned* a, unsigned b0, unsigned b1) {
    asm volatile(
        "mma.sync.aligned.m16n8k8.row.col.f32.tf32.tf32.f32 "
        "{%0,%1,%2,%3}, {%4,%5,%6,%7}, {%8,%9}, {%0,%1,%2,%3};\n"
        : "+f"(c[0]), "+f"(c[1]), "+f"(c[2]), "+f"(c[3])
        : "r"(a[0]), "r"(a[1]), "r"(a[2]), "r"(a[3]), "r"(b0), "r"(b1));
}

__device__ __forceinline__ void ldsm4(unsigned* r, unsigned saddr) {
    asm volatile("ldmatrix.sync.aligned.m8n8.x4.shared.b16 {%0,%1,%2,%3}, [%4];"
                 : "=r"(r[0]), "=r"(r[1]), "=r"(r[2]), "=r"(r[3]) : "r"(saddr));
}

__device__ __forceinline__ void cp16(float* smem_dst, const float* gsrc) {
    unsigned s = (unsigned)__cvta_generic_to_shared(smem_dst);
    asm volatile("cp.async.cg.shared.global [%0], [%1], 16;\n" :: "r"(s), "l"(gsrc));
}
#define CP_COMMIT() asm volatile("cp.async.commit_group;\n" ::: "memory")
#define CP_WAIT2()  asm volatile("cp.async.wait_group 2;\n" ::: "memory")

__device__ __forceinline__ float gelu_exact(float v) {
    return 0.5f * v * (1.0f + erff(v * 0.70710678118654752f));
}

__device__ __forceinline__ size_t tok_of(int r, int e) {
    int b = r >> 10;
    int tt = r & 1023;
    return (size_t)b * SEQ + (size_t)e * NPE + tt;
}

// ---------------------------------------------------------------------------
// Kernel 0: round weights to tf32 once (copies into g_w1/g_w2)
// ---------------------------------------------------------------------------
__global__ void prep_kernel(const float* __restrict__ w1, const float* __restrict__ w2) {
    size_t i = ((size_t)blockIdx.x * blockDim.x + threadIdx.x) * 4;
    if (i >= (size_t)INNER * DIM) return;
    float4 a = *(const float4*)(w1 + i);
    float4 b = *(const float4*)(w2 + i);
    a.x = rna_tf32(a.x); a.y = rna_tf32(a.y); a.z = rna_tf32(a.z); a.w = rna_tf32(a.w);
    b.x = rna_tf32(b.x); b.y = rna_tf32(b.y); b.z = rna_tf32(b.z); b.w = rna_tf32(b.w);
    *(float4*)(g_w1 + i) = a;
    *(float4*)(g_w2 + i) = b;
}

// ---------------------------------------------------------------------------
// Kernel 1: LayerNorm (one block/token), writes rna-tf32 h, residual default out=x
// ---------------------------------------------------------------------------
__global__ void ln_kernel(const float* __restrict__ x,
                          const float* __restrict__ nw,
                          const float* __restrict__ nb,
                          float* __restrict__ out) {
    size_t g = blockIdx.x;
    int t = threadIdx.x;
    const float4* xp = reinterpret_cast<const float4*>(x + g * DIM);
    float4 v = xp[t];
    float s  = v.x + v.y + v.z + v.w;
    float sq = v.x * v.x + v.y * v.y + v.z * v.z + v.w * v.w;
    #pragma unroll
    for (int o = 16; o; o >>= 1) {
        s  += __shfl_xor_sync(0xffffffffu, s,  o);
        sq += __shfl_xor_sync(0xffffffffu, sq, o);
    }
    __shared__ float ss[8], ssq[8];
    __shared__ float mu_s, rs_s;
    int wid = t >> 5, lid = t & 31;
    if (lid == 0) { ss[wid] = s; ssq[wid] = sq; }
    __syncthreads();
    if (t == 0) {
        float S = 0.f, SQ = 0.f;
        #pragma unroll
        for (int i = 0; i < 8; i++) { S += ss[i]; SQ += ssq[i]; }
        float mu = S * (1.0f / DIM);
        float var = SQ * (1.0f / DIM) - mu * mu;
        mu_s = mu;
        rs_s = rsqrtf(var + 1e-5f);
    }
    __syncthreads();
    float mu = mu_s, rs = rs_s;
    float4 wv = reinterpret_cast<const float4*>(nw)[t];
    float4 bv = reinterpret_cast<const float4*>(nb)[t];
    float4 h;
    h.x = rna_tf32((v.x - mu) * rs * wv.x + bv.x);
    h.y = rna_tf32((v.y - mu) * rs * wv.y + bv.y);
    h.z = rna_tf32((v.z - mu) * rs * wv.z + bv.z);
    h.w = rna_tf32((v.w - mu) * rs * wv.w + bv.w);
    reinterpret_cast<float4*>(g_h + g * DIM)[t] = h;
    reinterpret_cast<float4*>(out + g * DIM)[t] = v;
}

// ---------------------------------------------------------------------------
// Shared GEMM mainloop pieces (cp.async 4-stage + ldmatrix fragments)
// ---------------------------------------------------------------------------
struct Frag { float acc[4][4][4]; };

__device__ __forceinline__ void compute_tile(float acc[4][4][4],
                                             unsigned aBase, unsigned bBase,
                                             int mBase, int nBase, int lrow, int lhalf) {
    #pragma unroll
    for (int ks = 0; ks < 2; ++ks) {
        const int kb = ks * 32 + lhalf * 16;
        unsigned a[4][4];
        #pragma unroll
        for (int mi = 0; mi < 4; ++mi)
            ldsm4(a[mi], aBase + (unsigned)((mBase + mi * 16 + lrow) * SKW * 4 + kb));
        unsigned t0[4], t1[4];
        ldsm4(t0, bBase + (unsigned)((nBase + lrow) * SKW * 4 + kb));
        ldsm4(t1, bBase + (unsigned)((nBase + 16 + lrow) * SKW * 4 + kb));
        #pragma unroll
        for (int mi = 0; mi < 4; ++mi) {
            mma8(acc[mi][0], a[mi], t0[0], t0[2]);
            mma8(acc[mi][1], a[mi], t0[1], t0[3]);
            mma8(acc[mi][2], a[mi], t1[0], t1[2]);
            mma8(acc[mi][3], a[mi], t1[1], t1[3]);
        }
    }
}

// ---------------------------------------------------------------------------
// Kernel 2: gemm1_all  inner[e] = gelu( h[:, :K] @ w1[:, :K]^T + b1 )
// grid (INNER/BN, MROWS/BM, NEXP)
// ---------------------------------------------------------------------------
__global__ __launch_bounds__(256, 2)
void gemm1_all(const float* __restrict__ l1b) {
    extern __shared__ float smem[];
    float* As = smem;
    float* Bs = smem + STAGES * BM * SKW;

    const int e  = blockIdx.z;
    const int KT = (DIM >> e) / BK;
    const int tid  = threadIdx.x;
    const int srow = tid >> 2;
    const int skq  = tid & 3;

    const float* aA0 = g_h + tok_of(blockIdx.y * BM + srow, e) * DIM + skq * 4;
    const float* aA1 = g_h + tok_of(blockIdx.y * BM + srow + 64, e) * DIM + skq * 4;
    const float* aB0 = g_w1 + (size_t)(blockIdx.x * BN + srow) * DIM + skq * 4;
    const float* aB1 = aB0 + (size_t)64 * DIM;

    const int so0 = srow * SKW + skq * 4;
    const int so1 = (srow + 64) * SKW + skq * 4;

    #pragma unroll
    for (int s = 0; s < STAGES - 1; ++s) {
        if (s < KT) {
            float* a = As + s * BM * SKW;
            float* b = Bs + s * BN * SKW;
            size_t off = (size_t)s * BK;
            cp16(a + so0, aA0 + off); cp16(a + so1, aA1 + off);
            cp16(b + so0, aB0 + off); cp16(b + so1, aB1 + off);
        }
        CP_COMMIT();
    }

    const int wid = tid >> 5, lane = tid & 31;
    const int mBase = (wid & 1) * 64;
    const int nBase = (wid >> 1) * 32;
    const int lrow = lane & 15;
    const int lhalf = lane >> 4;
    const unsigned aS = (unsigned)__cvta_generic_to_shared(As);
    const unsigned bS = (unsigned)__cvta_generic_to_shared(Bs);

    float acc[4][4][4];
    #pragma unroll
    for (int i = 0; i < 4; i++)
        #pragma unroll
        for (int j = 0; j < 4; j++)
            #pragma unroll
            for (int k = 0; k < 4; k++) acc[i][j][k] = 0.f;

    for (int kt = 0; kt < KT; ++kt) {
        CP_WAIT2();
        __syncthreads();
        const int pf = kt + STAGES - 1;
        if (pf < KT) {
            const int sb = pf & (STAGES - 1);
            float* a = As + sb * BM * SKW;
            float* b = Bs + sb * BN * SKW;
            size_t off = (size_t)pf * BK;
            cp16(a + so0, aA0 + off); cp16(a + so1, aA1 + off);
            cp16(b + so0, aB0 + off); cp16(b + so1, aB1 + off);
        }
        CP_COMMIT();
        const unsigned st = (unsigned)((kt & (STAGES - 1)) * BM * SKW * 4);
        compute_tile(acc, aS + st, bS + st, mBase, nBase, lrow, lhalf);
    }

    // epilogue: bias + exact gelu, rna-rounded, into g_inner slab e
    float* innE = g_inner + (size_t)e * MROWS * INNER;
    const int lm = lane >> 2, lk = lane & 3;
    const int rT = blockIdx.y * BM + mBase;
    const int cT = blockIdx.x * BN + nBase;
    #pragma unroll
    for (int mi = 0; mi < 4; mi++) {
        int r0 = rT + mi * 16 + lm;
        #pragma unroll
        for (int ni = 0; ni < 4; ni++) {
            int c0 = cT + ni * 8 + lk * 2;
            float bv0 = l1b[c0], bv1 = l1b[c0 + 1];
            float2 lo = make_float2(rna_tf32(gelu_exact(acc[mi][ni][0] + bv0)),
                                    rna_tf32(gelu_exact(acc[mi][ni][1] + bv1)));
            float2 hi = make_float2(rna_tf32(gelu_exact(acc[mi][ni][2] + bv0)),
                                    rna_tf32(gelu_exact(acc[mi][ni][3] + bv1)));
            *(float2*)&innE[(size_t)r0 * INNER + c0]       = lo;
            *(float2*)&innE[(size_t)(r0 + 8) * INNER + c0] = hi;
        }
    }
}

// ---------------------------------------------------------------------------
// Kernel 3: gemm2_all  out[:, :m] = x + scale * ( inner[e] @ w2[:m,:]^T + b2[:m] )
// grid (DIM/BN, MROWS/BM, NEXP); blocks beyond m/BN exit
// ---------------------------------------------------------------------------
__global__ __launch_bounds__(256, 2)
void gemm2_all(const float* __restrict__ x,
               const float* __restrict__ rp,
               const float* __restrict__ alpha_p,
               const float* __restrict__ l2b,
               float* __restrict__ out) {
    const int e = blockIdx.z;
    const int m = DIM >> e;
    if (blockIdx.x * BN >= m) return;

    extern __shared__ float smem[];
    float* As = smem;
    float* Bs = smem + STAGES * BM * SKW;

    const int KT = INNER / BK;     // 256
    const int tid  = threadIdx.x;
    const int srow = tid >> 2;
    const int skq  = tid & 3;

    const float* innE = g_inner + (size_t)e * MROWS * INNER;
    const float* aA0 = innE + (size_t)(blockIdx.y * BM + srow) * INNER + skq * 4;
    const float* aA1 = aA0 + (size_t)64 * INNER;
    const float* aB0 = g_w2 + (size_t)(blockIdx.x * BN + srow) * INNER + skq * 4;
    const float* aB1 = aB0 + (size_t)64 * INNER;

    const int so0 = srow * SKW + skq * 4;
    const int so1 = (srow + 64) * SKW + skq * 4;

    #pragma unroll
    for (int s = 0; s < STAGES - 1; ++s) {
        float* a = As + s * BM * SKW;
        float* b = Bs + s * BN * SKW;
        size_t off = (size_t)s * BK;
        cp16(a + so0, aA0 + off); cp16(a + so1, aA1 + off);
        cp16(b + so0, aB0 + off); cp16(b + so1, aB1 + off);
        CP_COMMIT();
    }

    const int wid = tid >> 5, lane = tid & 31;
    const int mBase = (wid & 1) * 64;
    const int nBase = (wid >> 1) * 32;
    const int lrow = lane & 15;
    const int lhalf = lane >> 4;
    const unsigned aS = (unsigned)__cvta_generic_to_shared(As);
    const unsigned bS = (unsigned)__cvta_generic_to_shared(Bs);

    float acc[4][4][4];
    #pragma unroll
    for (int i = 0; i < 4; i++)
        #pragma unroll
        for (int j = 0; j < 4; j++)
            #pragma unroll
            for (int k = 0; k < 4; k++) acc[i][j][k] = 0.f;

    for (int kt = 0; kt < KT; ++kt) {
        CP_WAIT2();
        __syncthreads();
        const int pf = kt + STAGES - 1;
        if (pf < KT) {
            const int sb = pf & (STAGES - 1);
            float* a = As + sb * BM * SKW;
            float* b = Bs + sb * BN * SKW;
            size_t off = (size_t)pf * BK;
            cp16(a + so0, aA0 + off); cp16(a + so1, aA1 + off);
            cp16(b + so0, aB0 + off); cp16(b + so1, aB1 + off);
        }
        CP_COMMIT();
        const unsigned st = (unsigned)((kt & (STAGES - 1)) * BM * SKW * 4);
        compute_tile(acc, aS + st, bS + st, mBase, nBase, lrow, lhalf);
    }

    const float al = *alpha_p;
    const int lm = lane >> 2, lk = lane & 3;
    const int rT = blockIdx.y * BM + mBase;
    const int cT = blockIdx.x * BN + nBase;
    #pragma unroll
    for (int mi = 0; mi < 4; mi++) {
        int rloc = rT + mi * 16 + lm;
        size_t g0 = tok_of(rloc, e);
        size_t g1 = tok_of(rloc + 8, e);
        float sc0 = al * rp[g0 * NEXP + e] + 1.0f;
        float sc1 = al * rp[g1 * NEXP + e] + 1.0f;
        #pragma unroll
        for (int ni = 0; ni < 4; ni++) {
            int c0 = cT + ni * 8 + lk * 2;
            float bv0 = l2b[c0], bv1 = l2b[c0 + 1];
            float2 xv0 = *(const float2*)&x[g0 * DIM + c0];
            float2 xv1 = *(const float2*)&x[g1 * DIM + c0];
            float2 o0 = make_float2(xv0.x + sc0 * (acc[mi][ni][0] + bv0),
                                    xv0.y + sc0 * (acc[mi][ni][1] + bv1));
            float2 o1 = make_float2(xv1.x + sc1 * (acc[mi][ni][2] + bv0),
                                    xv1.y + sc1 * (acc[mi][ni][3] + bv1));
            *(float2*)&out[g0 * DIM + c0] = o0;
            *(float2*)&out[g1 * DIM + c0] = o1;
        }
    }
}

// ---------------------------------------------------------------------------
extern "C" void kernel_launch(void* const* d_in, const int* in_sizes, int n_in,
                              void* d_out, int out_size) {
    const float* x     = (const float*)d_in[0];
    const float* rp    = (const float*)d_in[1];
    const float* alpha = (const float*)d_in[2];
    const float* nw    = (const float*)d_in[3];
    const float* nb    = (const float*)d_in[4];
    const float* l1w   = (const float*)d_in[5];
    const float* l1b   = (const float*)d_in[6];
    const float* l2w   = (const float*)d_in[7];
    const float* l2b   = (const float*)d_in[8];
    float* out = (float*)d_out;

    static bool attr_done = false;
    if (!attr_done) {
        cudaFuncSetAttribute(gemm1_all, cudaFuncAttributeMaxDynamicSharedMemorySize, SMEM_BYTES);
        cudaFuncSetAttribute(gemm2_all, cudaFuncAttributeMaxDynamicSharedMemorySize, SMEM_BYTES);
        attr_done = true;
    }

    prep_kernel<<<(INNER * DIM / 4 + 255) / 256, 256>>>(l1w, l2w);
    ln_kernel<<<BATCH * SEQ, 256>>>(x, nw, nb, out);

    dim3 g1(INNER / BN, MROWS / BM, NEXP);   // (32, 64, 4)
    gemm1_all<<<g1, 256, SMEM_BYTES>>>(l1b);
    dim3 g2(DIM / BN, MROWS / BM, NEXP);     // (8, 64, 4)
    gemm2_all<<<g2, 256, SMEM_BYTES>>>(x, rp, alpha, l2b, out);
}

// round 5
// speedup vs baseline: 2.4437x; 1.7667x over previous
#include <cuda_runtime.h>
#include <cuda_fp16.h>
#include <math.h>
#include <stdint.h>

// Problem constants
#define DIM    1024
#define NEXP   4
#define BATCH  8
#define SEQ    4096
#define NPE    1024
#define MROWS  8192
#define INNER  4096

#define BM 128
#define BN 128
#define BK 32                // halves per k-tile
#define SKH 40               // halves per smem row (32 + 8 pad) -> 80B stride, conflict-free
#define STAGES 4
#define TILE_HALVES (128 * SKH)                   // per operand per stage
#define SMEM_HALVES (2 * STAGES * TILE_HALVES)
#define SMEM_BYTES  (SMEM_HALVES * 2)             // 81920

// Scratch (device globals; allocation-free)
__device__ __half g_hh[(size_t)BATCH * SEQ * DIM];           // 64 MB
__device__ __half g_w1h[(size_t)INNER * DIM];                // 8 MB
__device__ __half g_w2h[(size_t)DIM * INNER];                // 8 MB
__device__ __half g_inner[(size_t)NEXP * MROWS * INNER];     // 256 MB

// ---------------------------------------------------------------------------
__device__ __forceinline__ uint32_t pack2(float a, float b) {
    __half2 h = __floats2half2_rn(a, b);
    return *reinterpret_cast<uint32_t*>(&h);
}

__device__ __forceinline__ void mma16(float* c, const uint32_t* a, uint32_t b0, uint32_t b1) {
    asm volatile(
        "mma.sync.aligned.m16n8k16.row.col.f32.f16.f16.f32 "
        "{%0,%1,%2,%3}, {%4,%5,%6,%7}, {%8,%9}, {%0,%1,%2,%3};\n"
        : "+f"(c[0]), "+f"(c[1]), "+f"(c[2]), "+f"(c[3])
        : "r"(a[0]), "r"(a[1]), "r"(a[2]), "r"(a[3]), "r"(b0), "r"(b1));
}

__device__ __forceinline__ void ldsm4(uint32_t* r, uint32_t saddr) {
    asm volatile("ldmatrix.sync.aligned.m8n8.x4.shared.b16 {%0,%1,%2,%3}, [%4];"
                 : "=r"(r[0]), "=r"(r[1]), "=r"(r[2]), "=r"(r[3]) : "r"(saddr));
}

__device__ __forceinline__ void cp16(__half* smem_dst, const __half* gsrc) {
    unsigned s = (unsigned)__cvta_generic_to_shared(smem_dst);
    asm volatile("cp.async.cg.shared.global [%0], [%1], 16;\n" :: "r"(s), "l"(gsrc));
}
#define CP_COMMIT() asm volatile("cp.async.commit_group;\n" ::: "memory")
#define CP_WAIT2()  asm volatile("cp.async.wait_group 2;\n" ::: "memory")

__device__ __forceinline__ float gelu_exact(float v) {
    return 0.5f * v * (1.0f + erff(v * 0.70710678118654752f));
}
__device__ __forceinline__ size_t tok_of(int r, int e) {
    return (size_t)(r >> 10) * SEQ + (size_t)e * NPE + (r & 1023);
}

// ---------------------------------------------------------------------------
// prep: round weights to half
// ---------------------------------------------------------------------------
__global__ void prep_kernel(const float* __restrict__ w1, const float* __restrict__ w2) {
    size_t i = ((size_t)blockIdx.x * blockDim.x + threadIdx.x) * 4;
    if (i >= (size_t)INNER * DIM) return;
    float4 a = *(const float4*)(w1 + i);
    float4 b = *(const float4*)(w2 + i);
    *(uint2*)(g_w1h + i) = make_uint2(pack2(a.x, a.y), pack2(a.z, a.w));
    *(uint2*)(g_w2h + i) = make_uint2(pack2(b.x, b.y), pack2(b.z, b.w));
}

// ---------------------------------------------------------------------------
// LayerNorm -> half h; residual default out = x
// ---------------------------------------------------------------------------
__global__ void ln_kernel(const float* __restrict__ x,
                          const float* __restrict__ nw,
                          const float* __restrict__ nb,
                          float* __restrict__ out) {
    size_t g = blockIdx.x;
    int t = threadIdx.x;
    const float4* xp = reinterpret_cast<const float4*>(x + g * DIM);
    float4 v = xp[t];
    float s  = v.x + v.y + v.z + v.w;
    float sq = v.x * v.x + v.y * v.y + v.z * v.z + v.w * v.w;
    #pragma unroll
    for (int o = 16; o; o >>= 1) {
        s  += __shfl_xor_sync(0xffffffffu, s,  o);
        sq += __shfl_xor_sync(0xffffffffu, sq, o);
    }
    __shared__ float ss[8], ssq[8];
    __shared__ float mu_s, rs_s;
    int wid = t >> 5, lid = t & 31;
    if (lid == 0) { ss[wid] = s; ssq[wid] = sq; }
    __syncthreads();
    if (t == 0) {
        float S = 0.f, SQ = 0.f;
        #pragma unroll
        for (int i = 0; i < 8; i++) { S += ss[i]; SQ += ssq[i]; }
        float mu = S * (1.0f / DIM);
        float var = SQ * (1.0f / DIM) - mu * mu;
        mu_s = mu; rs_s = rsqrtf(var + 1e-5f);
    }
    __syncthreads();
    float mu = mu_s, rs = rs_s;
    float4 wv = reinterpret_cast<const float4*>(nw)[t];
    float4 bv = reinterpret_cast<const float4*>(nb)[t];
    float h0 = (v.x - mu) * rs * wv.x + bv.x;
    float h1 = (v.y - mu) * rs * wv.y + bv.y;
    float h2 = (v.z - mu) * rs * wv.z + bv.z;
    float h3 = (v.w - mu) * rs * wv.w + bv.w;
    *(uint2*)(g_hh + g * DIM + t * 4) = make_uint2(pack2(h0, h1), pack2(h2, h3));
    reinterpret_cast<float4*>(out + g * DIM)[t] = v;
}

// ---------------------------------------------------------------------------
// fp16 HMMA compute core: one 32-half k-tile
// warp tile 64x32; A frags via ldmatrix.x4 (16x16), B via ldmatrix.x4 (n16 x k16)
// ---------------------------------------------------------------------------
__device__ __forceinline__ void compute_tile(float acc[4][4][4],
                                             const __half* As, const __half* Bs,
                                             int mBase, int nBase, int lrow, int lhalf) {
    const unsigned aS = (unsigned)__cvta_generic_to_shared(As);
    const unsigned bS = (unsigned)__cvta_generic_to_shared(Bs);
    #pragma unroll
    for (int ks = 0; ks < 2; ++ks) {
        const int kb = ks * 32 + lhalf * 16;      // byte offset in row
        uint32_t a[4][4];
        #pragma unroll
        for (int mi = 0; mi < 4; ++mi)
            ldsm4(a[mi], aS + (unsigned)((mBase + mi * 16 + lrow) * (SKH * 2) + kb));
        uint32_t t0[4], t1[4];
        ldsm4(t0, bS + (unsigned)((nBase + lrow) * (SKH * 2) + kb));
        ldsm4(t1, bS + (unsigned)((nBase + 16 + lrow) * (SKH * 2) + kb));
        #pragma unroll
        for (int mi = 0; mi < 4; ++mi) {
            mma16(acc[mi][0], a[mi], t0[0], t0[2]);
            mma16(acc[mi][1], a[mi], t0[1], t0[3]);
            mma16(acc[mi][2], a[mi], t1[0], t1[2]);
            mma16(acc[mi][3], a[mi], t1[1], t1[3]);
        }
    }
}

// ---------------------------------------------------------------------------
// GEMM1: inner[e] = gelu( h[:, :K] @ w1[:, :K]^T + b1 )   grid (32, 64, 4)
// ---------------------------------------------------------------------------
__global__ __launch_bounds__(256, 2)
void gemm1_fp16(const float* __restrict__ l1b) {
    extern __shared__ __half smem[];
    __half* As = smem;
    __half* Bs = smem + STAGES * TILE_HALVES;

    const int e  = blockIdx.z;
    const int KT = 32 >> e;                       // (1024>>e)/32
    const int tid  = threadIdx.x;
    const int srow = tid >> 2;                    // 0..63
    const int chk  = tid & 3;                     // 8-half chunk

    const __half* aA0 = g_hh + tok_of(blockIdx.y * BM + srow, e) * DIM + chk * 8;
    const __half* aA1 = g_hh + tok_of(blockIdx.y * BM + srow + 64, e) * DIM + chk * 8;
    const __half* aB0 = g_w1h + (size_t)(blockIdx.x * BN + srow) * DIM + chk * 8;
    const __half* aB1 = aB0 + (size_t)64 * DIM;

    const int so0 = srow * SKH + chk * 8;
    const int so1 = (srow + 64) * SKH + chk * 8;

    #pragma unroll
    for (int s = 0; s < STAGES - 1; ++s) {
        if (s < KT) {
            __half* a = As + s * TILE_HALVES;
            __half* b = Bs + s * TILE_HALVES;
            size_t off = (size_t)s * BK;
            cp16(a + so0, aA0 + off); cp16(a + so1, aA1 + off);
            cp16(b + so0, aB0 + off); cp16(b + so1, aB1 + off);
        }
        CP_COMMIT();
    }

    const int wid = tid >> 5, lane = tid & 31;
    const int mBase = (wid & 1) * 64;
    const int nBase = (wid >> 1) * 32;
    const int lrow = lane & 15, lhalf = lane >> 4;

    float acc[4][4][4];
    #pragma unroll
    for (int i = 0; i < 4; i++)
        #pragma unroll
        for (int j = 0; j < 4; j++)
            #pragma unroll
            for (int k = 0; k < 4; k++) acc[i][j][k] = 0.f;

    for (int kt = 0; kt < KT; ++kt) {
        CP_WAIT2();
        __syncthreads();
        const int pf = kt + STAGES - 1;
        if (pf < KT) {
            const int sb = pf & (STAGES - 1);
            __half* a = As + sb * TILE_HALVES;
            __half* b = Bs + sb * TILE_HALVES;
            size_t off = (size_t)pf * BK;
            cp16(a + so0, aA0 + off); cp16(a + so1, aA1 + off);
            cp16(b + so0, aB0 + off); cp16(b + so1, aB1 + off);
        }
        CP_COMMIT();
        const int st = kt & (STAGES - 1);
        compute_tile(acc, As + st * TILE_HALVES, Bs + st * TILE_HALVES,
                     mBase, nBase, lrow, lhalf);
    }

    // epilogue: bias + gelu -> half
    __half* innE = g_inner + (size_t)e * MROWS * INNER;
    const int lm = lane >> 2, lk = lane & 3;
    const int rT = blockIdx.y * BM + mBase;
    const int cT = blockIdx.x * BN + nBase;
    #pragma unroll
    for (int mi = 0; mi < 4; mi++) {
        int r0 = rT + mi * 16 + lm;
        #pragma unroll
        for (int ni = 0; ni < 4; ni++) {
            int c0 = cT + ni * 8 + lk * 2;
            float bv0 = __ldg(l1b + c0), bv1 = __ldg(l1b + c0 + 1);
            uint32_t lo = pack2(gelu_exact(acc[mi][ni][0] + bv0),
                                gelu_exact(acc[mi][ni][1] + bv1));
            uint32_t hi = pack2(gelu_exact(acc[mi][ni][2] + bv0),
                                gelu_exact(acc[mi][ni][3] + bv1));
            *(uint32_t*)&innE[(size_t)r0 * INNER + c0]       = lo;
            *(uint32_t*)&innE[(size_t)(r0 + 8) * INNER + c0] = hi;
        }
    }
}

// ---------------------------------------------------------------------------
// GEMM2: out[:, :m] = x + scale*( inner[e] @ w2[:m,:]^T + b2[:m] )
// grid (15, 64): slots 0-7 e0, 8-11 e1, 12-13 e2, 14 e3
// ---------------------------------------------------------------------------
__global__ __launch_bounds__(256, 2)
void gemm2_fp16(const float* __restrict__ x,
                const float* __restrict__ rp,
                const float* __restrict__ alpha_p,
                const float* __restrict__ l2b,
                float* __restrict__ out) {
    extern __shared__ __half smem[];
    __half* As = smem;
    __half* Bs = smem + STAGES * TILE_HALVES;

    const int slot = blockIdx.x;
    int e, nx;
    if (slot < 8)       { e = 0; nx = slot; }
    else if (slot < 12) { e = 1; nx = slot - 8; }
    else if (slot < 14) { e = 2; nx = slot - 12; }
    else                { e = 3; nx = 0; }

    const int KT = INNER / BK;     // 128
    const int tid  = threadIdx.x;
    const int srow = tid >> 2;
    const int chk  = tid & 3;

    const __half* innE = g_inner + (size_t)e * MROWS * INNER;
    const __half* aA0 = innE + (size_t)(blockIdx.y * BM + srow) * INNER + chk * 8;
    const __half* aA1 = aA0 + (size_t)64 * INNER;
    const __half* aB0 = g_w2h + (size_t)(nx * BN + srow) * INNER + chk * 8;
    const __half* aB1 = aB0 + (size_t)64 * INNER;

    const int so0 = srow * SKH + chk * 8;
    const int so1 = (srow + 64) * SKH + chk * 8;

    #pragma unroll
    for (int s = 0; s < STAGES - 1; ++s) {
        __half* a = As + s * TILE_HALVES;
        __half* b = Bs + s * TILE_HALVES;
        size_t off = (size_t)s * BK;
        cp16(a + so0, aA0 + off); cp16(a + so1, aA1 + off);
        cp16(b + so0, aB0 + off); cp16(b + so1, aB1 + off);
        CP_COMMIT();
    }

    const int wid = tid >> 5, lane = tid & 31;
    const int mBase = (wid & 1) * 64;
    const int nBase = (wid >> 1) * 32;
    const int lrow = lane & 15, lhalf = lane >> 4;

    float acc[4][4][4];
    #pragma unroll
    for (int i = 0; i < 4; i++)
        #pragma unroll
        for (int j = 0; j < 4; j++)
            #pragma unroll
            for (int k = 0; k < 4; k++) acc[i][j][k] = 0.f;

    for (int kt = 0; kt < KT; ++kt) {
        CP_WAIT2();
        __syncthreads();
        const int pf = kt + STAGES - 1;
        if (pf < KT) {
            const int sb = pf & (STAGES - 1);
            __half* a = As + sb * TILE_HALVES;
            __half* b = Bs + sb * TILE_HALVES;
            size_t off = (size_t)pf * BK;
            cp16(a + so0, aA0 + off); cp16(a + so1, aA1 + off);
            cp16(b + so0, aB0 + off); cp16(b + so1, aB1 + off);
        }
        CP_COMMIT();
        const int st = kt & (STAGES - 1);
        compute_tile(acc, As + st * TILE_HALVES, Bs + st * TILE_HALVES,
                     mBase, nBase, lrow, lhalf);
    }

    const float al = __ldg(alpha_p);
    const int lm = lane >> 2, lk = lane & 3;
    const int rT = blockIdx.y * BM + mBase;
    const int cT = nx * BN + nBase;
    #pragma unroll
    for (int mi = 0; mi < 4; mi++) {
        int rloc = rT + mi * 16 + lm;
        size_t g0 = tok_of(rloc, e);
        size_t g1 = tok_of(rloc + 8, e);
        float sc0 = al * __ldg(rp + g0 * NEXP + e) + 1.0f;
        float sc1 = al * __ldg(rp + g1 * NEXP + e) + 1.0f;
        #pragma unroll
        for (int ni = 0; ni < 4; ni++) {
            int c0 = cT + ni * 8 + lk * 2;
            float bv0 = __ldg(l2b + c0), bv1 = __ldg(l2b + c0 + 1);
            float2 xv0 = *(const float2*)&x[g0 * DIM + c0];
            float2 xv1 = *(const float2*)&x[g1 * DIM + c0];
            float2 o0 = make_float2(xv0.x + sc0 * (acc[mi][ni][0] + bv0),
                                    xv0.y + sc0 * (acc[mi][ni][1] + bv1));
            float2 o1 = make_float2(xv1.x + sc1 * (acc[mi][ni][2] + bv0),
                                    xv1.y + sc1 * (acc[mi][ni][3] + bv1));
            *(float2*)&out[g0 * DIM + c0] = o0;
            *(float2*)&out[g1 * DIM + c0] = o1;
        }
    }
}

// ---------------------------------------------------------------------------
extern "C" void kernel_launch(void* const* d_in, const int* in_sizes, int n_in,
                              void* d_out, int out_size) {
    const float* x     = (const float*)d_in[0];
    const float* rp    = (const float*)d_in[1];
    const float* alpha = (const float*)d_in[2];
    const float* nw    = (const float*)d_in[3];
    const float* nb    = (const float*)d_in[4];
    const float* l1w   = (const float*)d_in[5];
    const float* l1b   = (const float*)d_in[6];
    const float* l2w   = (const float*)d_in[7];
    const float* l2b   = (const float*)d_in[8];
    float* out = (float*)d_out;

    static bool attr_done = false;
    if (!attr_done) {
        cudaFuncSetAttribute(gemm1_fp16, cudaFuncAttributeMaxDynamicSharedMemorySize, SMEM_BYTES);
        cudaFuncSetAttribute(gemm2_fp16, cudaFuncAttributeMaxDynamicSharedMemorySize, SMEM_BYTES);
        attr_done = true;
    }

    prep_kernel<<<(INNER * DIM / 4 + 255) / 256, 256>>>(l1w, l2w);
    ln_kernel<<<BATCH * SEQ, 256>>>(x, nw, nb, out);

    dim3 g1(INNER / BN, MROWS / BM, NEXP);   // (32, 64, 4)
    gemm1_fp16<<<g1, 256, SMEM_BYTES>>>(l1b);
    dim3 g2(15, MROWS / BM);                 // fused expert/n-block slots
    gemm2_fp16<<<g2, 256, SMEM_BYTES>>>(x, rp, alpha, l2b, out);
}